// round 1
// baseline (speedup 1.0000x reference)
#include <cuda_runtime.h>

#define GD 160
#define GH 160
#define GW 160
#define CIN 32
#define COUT 64
#define NK 27
#define TILE_V 128

// Dense voxel -> row-index grid (16.4 MB). Device global: allowed scratch.
__device__ int g_grid[GD * GH * GW];

__global__ void init_grid_kernel() {
    int i = blockIdx.x * blockDim.x + threadIdx.x;
    int4* p = reinterpret_cast<int4*>(g_grid);
    const int total = (GD * GH * GW) / 4;  // 1,024,000
    if (i < total) p[i] = make_int4(-1, -1, -1, -1);
}

__global__ void scatter_kernel(const int* __restrict__ coors, int n) {
    int i = blockIdx.x * blockDim.x + threadIdx.x;
    if (i < n) {
        int z = coors[4 * i + 1];
        int y = coors[4 * i + 2];
        int x = coors[4 * i + 3];
        g_grid[(z * GH + y) * GW + x] = i;
    }
}

// Block: 256 threads. Tile: 128 voxels x 64 couts.
// Thread (tx = tid&7, ty = tid>>3) owns voxels [ty*4, ty*4+4) x couts [tx*8, tx*8+8).
__global__ __launch_bounds__(256) void conv_kernel(
    const float* __restrict__ feat,
    const int*   __restrict__ coors,
    const float* __restrict__ weight,
    const float* __restrict__ bias,
    float*       __restrict__ out,
    int n)
{
    __shared__ float sF[TILE_V][33];       // padded: stride 33 -> conflict-free
    __shared__ float sW[CIN][COUT];        // 8 KB, restaged per k
    __shared__ int   sIdx[TILE_V];
    __shared__ int   sZ[TILE_V], sY[TILE_V], sX[TILE_V];

    const int tid = threadIdx.x;
    const int tx = tid & 7;    // cout group
    const int ty = tid >> 3;   // voxel group
    const int v0 = blockIdx.x * TILE_V;

    if (tid < TILE_V) {
        int v = v0 + tid;
        if (v < n) {
            sZ[tid] = coors[4 * v + 1];
            sY[tid] = coors[4 * v + 2];
            sX[tid] = coors[4 * v + 3];
        } else {
            sZ[tid] = -1000; sY[tid] = -1000; sX[tid] = -1000;
        }
    }

    float acc[4][8];
    {
        float b[8];
        #pragma unroll
        for (int j = 0; j < 8; j++) b[j] = bias[tx * 8 + j];
        #pragma unroll
        for (int i = 0; i < 4; i++)
            #pragma unroll
            for (int j = 0; j < 8; j++) acc[i][j] = b[j];
    }

    for (int k = 0; k < NK; k++) {
        const int dz = k / 9 - 1;
        const int dy = (k / 3) % 3 - 1;
        const int dx = k % 3 - 1;

        __syncthreads();  // protect sW/sF/sIdx from previous iteration readers

        // Stage W[k] (2048 floats) into smem: 2 float4 per thread.
        {
            const float4* wsrc = reinterpret_cast<const float4*>(weight + k * CIN * COUT);
            float4* wdst = reinterpret_cast<float4*>(&sW[0][0]);
            wdst[tid]       = wsrc[tid];
            wdst[tid + 256] = wsrc[tid + 256];
        }

        // Neighbor lookup for this k.
        if (tid < TILE_V) {
            int z = sZ[tid] + dz, y = sY[tid] + dy, x = sX[tid] + dx;
            int idx = -1;
            if ((unsigned)z < GD && (unsigned)y < GH && (unsigned)x < GW)
                idx = g_grid[(z * GH + y) * GW + x];
            sIdx[tid] = idx;
        }
        __syncthreads();

        // Gather: 128 voxels x 32 cin = 1024 float4 slots, 4 per thread.
        #pragma unroll
        for (int s = 0; s < 4; s++) {
            int slot = s * 256 + tid;
            int v  = slot >> 3;
            int c4 = slot & 7;
            int idx = sIdx[v];
            float4 val = make_float4(0.f, 0.f, 0.f, 0.f);
            if (idx >= 0)
                val = reinterpret_cast<const float4*>(feat)[idx * 8 + c4];
            sF[v][c4 * 4 + 0] = val.x;
            sF[v][c4 * 4 + 1] = val.y;
            sF[v][c4 * 4 + 2] = val.z;
            sF[v][c4 * 4 + 3] = val.w;
        }
        __syncthreads();

        // Compute: per cin: 2x LDS.128 weights + 4x scalar LDS features + 32 FFMA.
        #pragma unroll
        for (int c = 0; c < CIN; c++) {
            float4 wa = *reinterpret_cast<const float4*>(&sW[c][tx * 8]);
            float4 wb = *reinterpret_cast<const float4*>(&sW[c][tx * 8 + 4]);
            #pragma unroll
            for (int i = 0; i < 4; i++) {
                float f = sF[ty * 4 + i][c];
                acc[i][0] += f * wa.x;
                acc[i][1] += f * wa.y;
                acc[i][2] += f * wa.z;
                acc[i][3] += f * wa.w;
                acc[i][4] += f * wb.x;
                acc[i][5] += f * wb.y;
                acc[i][6] += f * wb.z;
                acc[i][7] += f * wb.w;
            }
        }
    }

    // Epilogue: 2 STG.128 per voxel.
    #pragma unroll
    for (int i = 0; i < 4; i++) {
        int v = v0 + ty * 4 + i;
        if (v < n) {
            float4 o0 = make_float4(acc[i][0], acc[i][1], acc[i][2], acc[i][3]);
            float4 o1 = make_float4(acc[i][4], acc[i][5], acc[i][6], acc[i][7]);
            float4* op = reinterpret_cast<float4*>(out);
            op[v * 16 + tx * 2 + 0] = o0;
            op[v * 16 + tx * 2 + 1] = o1;
        }
    }
}

extern "C" void kernel_launch(void* const* d_in, const int* in_sizes, int n_in,
                              void* d_out, int out_size) {
    const float* feat   = (const float*)d_in[0];
    const int*   coors  = (const int*)d_in[1];
    const float* weight = (const float*)d_in[2];
    const float* bias   = (const float*)d_in[3];
    float* out = (float*)d_out;
    const int n = in_sizes[0] / CIN;   // 400000

    init_grid_kernel<<<(GD * GH * GW / 4 + 255) / 256, 256>>>();
    scatter_kernel<<<(n + 255) / 256, 256>>>(coors, n);
    conv_kernel<<<(n + TILE_V - 1) / TILE_V, 256>>>(feat, coors, weight, bias, out, n);
}

// round 2
// speedup vs baseline: 1.0001x; 1.0001x over previous
#include <cuda_runtime.h>

#define GD 160
#define GH 160
#define GW 160
#define CIN 32
#define COUT 64
#define NK 27
#define TILE_V 128

// Dense voxel -> row-index grid (16.4 MB). Device global: allowed scratch.
__device__ int g_grid[GD * GH * GW];

__global__ void init_grid_kernel() {
    int i = blockIdx.x * blockDim.x + threadIdx.x;
    int4* p = reinterpret_cast<int4*>(g_grid);
    const int total = (GD * GH * GW) / 4;  // 1,024,000
    if (i < total) p[i] = make_int4(-1, -1, -1, -1);
}

__global__ void scatter_kernel(const int* __restrict__ coors, int n) {
    int i = blockIdx.x * blockDim.x + threadIdx.x;
    if (i < n) {
        int z = coors[4 * i + 1];
        int y = coors[4 * i + 2];
        int x = coors[4 * i + 3];
        g_grid[(z * GH + y) * GW + x] = i;
    }
}

// Block: 256 threads. Tile: 128 voxels x 64 couts.
// Thread (tx = tid&7, ty = tid>>3) owns voxels [ty*4, ty*4+4) x couts [tx*8, tx*8+8).
__global__ __launch_bounds__(256) void conv_kernel(
    const float* __restrict__ feat,
    const int*   __restrict__ coors,
    const float* __restrict__ weight,
    const float* __restrict__ bias,
    float*       __restrict__ out,
    int n)
{
    __shared__ float sF[TILE_V][33];       // padded: stride 33 -> conflict-free
    __shared__ float sW[CIN][COUT];        // 8 KB, restaged per k
    __shared__ int   sIdx[TILE_V];
    __shared__ int   sZ[TILE_V], sY[TILE_V], sX[TILE_V];

    const int tid = threadIdx.x;
    const int tx = tid & 7;    // cout group
    const int ty = tid >> 3;   // voxel group
    const int v0 = blockIdx.x * TILE_V;

    if (tid < TILE_V) {
        int v = v0 + tid;
        if (v < n) {
            sZ[tid] = coors[4 * v + 1];
            sY[tid] = coors[4 * v + 2];
            sX[tid] = coors[4 * v + 3];
        } else {
            sZ[tid] = -1000; sY[tid] = -1000; sX[tid] = -1000;
        }
    }

    float acc[4][8];
    {
        float b[8];
        #pragma unroll
        for (int j = 0; j < 8; j++) b[j] = bias[tx * 8 + j];
        #pragma unroll
        for (int i = 0; i < 4; i++)
            #pragma unroll
            for (int j = 0; j < 8; j++) acc[i][j] = b[j];
    }

    for (int k = 0; k < NK; k++) {
        const int dz = k / 9 - 1;
        const int dy = (k / 3) % 3 - 1;
        const int dx = k % 3 - 1;

        __syncthreads();  // protect sW/sF/sIdx from previous iteration readers

        // Stage W[k] (2048 floats) into smem: 2 float4 per thread.
        {
            const float4* wsrc = reinterpret_cast<const float4*>(weight + k * CIN * COUT);
            float4* wdst = reinterpret_cast<float4*>(&sW[0][0]);
            wdst[tid]       = wsrc[tid];
            wdst[tid + 256] = wsrc[tid + 256];
        }

        // Neighbor lookup for this k.
        if (tid < TILE_V) {
            int z = sZ[tid] + dz, y = sY[tid] + dy, x = sX[tid] + dx;
            int idx = -1;
            if ((unsigned)z < GD && (unsigned)y < GH && (unsigned)x < GW)
                idx = g_grid[(z * GH + y) * GW + x];
            sIdx[tid] = idx;
        }
        __syncthreads();

        // Gather: 128 voxels x 32 cin = 1024 float4 slots, 4 per thread.
        #pragma unroll
        for (int s = 0; s < 4; s++) {
            int slot = s * 256 + tid;
            int v  = slot >> 3;
            int c4 = slot & 7;
            int idx = sIdx[v];
            float4 val = make_float4(0.f, 0.f, 0.f, 0.f);
            if (idx >= 0)
                val = reinterpret_cast<const float4*>(feat)[idx * 8 + c4];
            sF[v][c4 * 4 + 0] = val.x;
            sF[v][c4 * 4 + 1] = val.y;
            sF[v][c4 * 4 + 2] = val.z;
            sF[v][c4 * 4 + 3] = val.w;
        }
        __syncthreads();

        // Compute: per cin: 2x LDS.128 weights + 4x scalar LDS features + 32 FFMA.
        #pragma unroll
        for (int c = 0; c < CIN; c++) {
            float4 wa = *reinterpret_cast<const float4*>(&sW[c][tx * 8]);
            float4 wb = *reinterpret_cast<const float4*>(&sW[c][tx * 8 + 4]);
            #pragma unroll
            for (int i = 0; i < 4; i++) {
                float f = sF[ty * 4 + i][c];
                acc[i][0] += f * wa.x;
                acc[i][1] += f * wa.y;
                acc[i][2] += f * wa.z;
                acc[i][3] += f * wa.w;
                acc[i][4] += f * wb.x;
                acc[i][5] += f * wb.y;
                acc[i][6] += f * wb.z;
                acc[i][7] += f * wb.w;
            }
        }
    }

    // Epilogue: 2 STG.128 per voxel.
    #pragma unroll
    for (int i = 0; i < 4; i++) {
        int v = v0 + ty * 4 + i;
        if (v < n) {
            float4 o0 = make_float4(acc[i][0], acc[i][1], acc[i][2], acc[i][3]);
            float4 o1 = make_float4(acc[i][4], acc[i][5], acc[i][6], acc[i][7]);
            float4* op = reinterpret_cast<float4*>(out);
            op[v * 16 + tx * 2 + 0] = o0;
            op[v * 16 + tx * 2 + 1] = o1;
        }
    }
}

extern "C" void kernel_launch(void* const* d_in, const int* in_sizes, int n_in,
                              void* d_out, int out_size) {
    const float* feat   = (const float*)d_in[0];
    const int*   coors  = (const int*)d_in[1];
    const float* weight = (const float*)d_in[2];
    const float* bias   = (const float*)d_in[3];
    float* out = (float*)d_out;
    const int n = in_sizes[0] / CIN;   // 400000

    init_grid_kernel<<<(GD * GH * GW / 4 + 255) / 256, 256>>>();
    scatter_kernel<<<(n + 255) / 256, 256>>>(coors, n);
    conv_kernel<<<(n + TILE_V - 1) / TILE_V, 256>>>(feat, coors, weight, bias, out, n);
}

// round 4
// speedup vs baseline: 2.4579x; 2.4577x over previous
#include <cuda_runtime.h>
#include <cuda_bf16.h>
#include <cstdint>

#define GD 160
#define GH 160
#define GW 160
#define CIN 32
#define COUT 64
#define NK 27
#define TILE_V 128
#define NMAX 400000

#if defined(__CUDA_ARCH_FEAT_SM103_ALL) || defined(__CUDA_ARCH_FEAT_SM100_ALL) || defined(__CUDA_ARCH_FEAT_SM101_ALL)
#define HAS_TCGEN05 1
#else
#define HAS_TCGEN05 0
#endif

// ---------------- device scratch (static globals: allowed) ----------------
__device__ int      g_grid[GD * GH * GW];        // 16.4 MB voxel -> row index
__device__ uint32_t g_packF[NMAX * CIN];         // 51.2 MB packed (bf16 hi | lo<<16)
__device__ uint32_t g_Bw[NK * 4096];             // 27 x 16KB pre-swizzled B tiles (pass1+pass2)

// ---------------- small PTX helpers ----------------
__device__ __forceinline__ uint32_t smem_u32(const void* p) {
    uint32_t a;
    asm("{ .reg .u64 t; cvta.to.shared.u64 t, %1; cvt.u32.u64 %0, t; }" : "=r"(a) : "l"(p));
    return a;
}

// SW128 swizzle
__host__ __device__ __forceinline__ uint32_t swz128(uint32_t off) {
    return off ^ ((off >> 3) & 0x70);
}

// SMEM descriptor: SW128, version=1, SBO=64 (1024B), LBO=1 (16B)
__device__ __forceinline__ uint64_t make_desc(uint32_t addr) {
    const uint64_t base =
        (uint64_t(2) << 61) | (uint64_t(1) << 46) | (uint64_t(64) << 32) | (uint64_t(1) << 16);
    return base | ((uint64_t)(addr >> 4) & 0x3FFF);
}

// idesc kind::f16: accum F32 (bit4), A=BF16 (bit7), B=BF16 (bit10), N=64 (8<<17), M=128 (8<<24)
#define MMA_IDESC 0x8100490u

#if HAS_TCGEN05
__device__ __forceinline__ void mma_f16_ss(uint32_t d_tmem, uint64_t a_desc,
                                           uint64_t b_desc, uint32_t en) {
    asm volatile(
        "{\n\t"
        ".reg .pred p;\n\t"
        "setp.ne.u32 p, %5, 0;\n\t"
        "tcgen05.mma.cta_group::1.kind::f16 [%0], %1, %2, %3, {%4, %4, %4, %4}, p;\n\t"
        "}"
        :: "r"(d_tmem), "l"(a_desc), "l"(b_desc), "r"(MMA_IDESC), "r"(0u), "r"(en)
        : "memory");
}
#endif

#define MBARRIER_WAIT_PARITY(mbar, parity) do {                                   \
    uint32_t _m = (mbar); uint32_t _p = (parity); uint32_t _done;                  \
    asm volatile(                                                                  \
        "{\n\t.reg .pred p;\n\t"                                                   \
        "mbarrier.try_wait.parity.acquire.cta.shared::cta.b64 p, [%1], %2;\n\t"    \
        "selp.b32 %0, 1, 0, p;\n\t}"                                               \
        : "=r"(_done) : "r"(_m), "r"(_p) : "memory");                              \
    if (!_done) {                                                                  \
        asm volatile(                                                              \
            "{\n\t.reg .pred P1;\n\t"                                              \
            "WL_%=:\n\t"                                                           \
            "mbarrier.try_wait.parity.acquire.cta.shared::cta.b64 P1, [%0], %1, 0x989680;\n\t" \
            "@P1 bra.uni WD_%=;\n\t"                                               \
            "bra.uni WL_%=;\n\t"                                                   \
            "WD_%=:\n\t}"                                                          \
            :: "r"(_m), "r"(_p) : "memory");                                       \
    }                                                                              \
} while (0)

// ---------------- prep kernels ----------------
__global__ void init_grid_kernel() {
    int i = blockIdx.x * blockDim.x + threadIdx.x;
    int4* p = reinterpret_cast<int4*>(g_grid);
    const int total = (GD * GH * GW) / 4;
    if (i < total) p[i] = make_int4(-1, -1, -1, -1);
}

__global__ void scatter_kernel(const int* __restrict__ coors, int n) {
    int i = blockIdx.x * blockDim.x + threadIdx.x;
    if (i < n) {
        int z = coors[4 * i + 1];
        int y = coors[4 * i + 2];
        int x = coors[4 * i + 3];
        g_grid[(z * GH + y) * GW + x] = i;
    }
}

__global__ void pack_features_kernel(const float* __restrict__ feat, int total) {
    int i = blockIdx.x * blockDim.x + threadIdx.x;
    if (i < total) {
        float x = feat[i];
        __nv_bfloat16 hi = __float2bfloat16(x);
        float r = x - __bfloat162float(hi);
        __nv_bfloat16 lo = __float2bfloat16(r);
        uint32_t w = (uint32_t)__bfloat16_as_ushort(hi) |
                     ((uint32_t)__bfloat16_as_ushort(lo) << 16);
        g_packF[i] = w;
    }
}

__global__ void pack_weights_kernel(const float* __restrict__ weight) {
    int i = blockIdx.x * blockDim.x + threadIdx.x;
    if (i >= NK * COUT * CIN) return;
    int k  = i / (COUT * CIN);
    int r  = i % (COUT * CIN);
    int nn = r / CIN;   // cout (B row)
    int c  = r % CIN;   // cin
    float w = weight[k * CIN * COUT + c * COUT + nn];
    __nv_bfloat16 hi = __float2bfloat16(w);
    float res = w - __bfloat162float(hi);
    __nv_bfloat16 lo = __float2bfloat16(res);
    uint32_t hb = __bfloat16_as_ushort(hi);
    uint32_t lb = __bfloat16_as_ushort(lo);
    uint32_t off = (uint32_t)(nn * 128 + c * 4);   // virtual cols 2c,2c+1
    uint32_t sw = swz128(off);
    g_Bw[k * 4096 + (sw >> 2)]        = hb | (hb << 16); // pass1: hi,hi
    g_Bw[k * 4096 + 2048 + (sw >> 2)] = lb;              // pass2: lo,0
}

// ---------------- main tensor-core kernel ----------------
// Block: 256 threads, tile = 128 voxels. out[128,64] accumulated in TMEM over 27 MMA groups.
__global__ __launch_bounds__(256) void conv_tc_kernel(
    const int*   __restrict__ coors,
    const float* __restrict__ bias,
    float*       __restrict__ out,
    int n)
{
#if HAS_TCGEN05
    // A tile: sBuf[0..4096)      (128 rows x 128B, SW128)
    // B1    : sBuf[4096..6144)   (64 rows x 128B, SW128)
    // B2    : sBuf[6144..8192)
    __shared__ __align__(1024) uint32_t sBuf[8192];
    __shared__ int   sIdx[TILE_V];
    __shared__ int   sZ[TILE_V], sY[TILE_V], sX[TILE_V];
    __shared__ float sBias[COUT];
    __shared__ uint32_t sTmem;
    __shared__ __align__(8) uint64_t sMbar;

    const int tid = threadIdx.x;
    const int v0  = blockIdx.x * TILE_V;

    const uint32_t mbarAddr = smem_u32(&sMbar);
    if (tid == 0) {
        asm volatile("mbarrier.init.shared.b64 [%0], 1;" :: "r"(mbarAddr) : "memory");
    }
    if (tid < COUT) sBias[tid] = bias[tid];
    if (tid < TILE_V) {
        int v = v0 + tid;
        if (v < n) {
            sZ[tid] = coors[4 * v + 1];
            sY[tid] = coors[4 * v + 2];
            sX[tid] = coors[4 * v + 3];
        } else {
            sZ[tid] = -1000; sY[tid] = -1000; sX[tid] = -1000;
        }
    }
    if (tid < 32) {
        uint32_t a = smem_u32(&sTmem);
        asm volatile("tcgen05.alloc.cta_group::1.sync.aligned.shared::cta.b32 [%0], %1;"
                     :: "r"(a), "r"(64u) : "memory");
        asm volatile("tcgen05.relinquish_alloc_permit.cta_group::1.sync.aligned;");
    }
    __syncthreads();

    const uint32_t tmem  = sTmem;
    const uint32_t aAddr = smem_u32(sBuf);
    const uint64_t aDesc  = make_desc(aAddr);
    const uint64_t b1Desc = make_desc(aAddr + 16384);
    const uint64_t b2Desc = make_desc(aAddr + 16384 + 8192);

    for (int k = 0; k < NK; k++) {
        if (k > 0) MBARRIER_WAIT_PARITY(mbarAddr, (k - 1) & 1);  // MMA k-1 done

        // Stage pre-swizzled B tiles (16KB): 1024 uint4, 4 per thread.
        {
            const uint4* src = reinterpret_cast<const uint4*>(g_Bw + k * 4096);
            uint4* dst = reinterpret_cast<uint4*>(sBuf + 4096);
            dst[tid]       = src[tid];
            dst[tid + 256] = src[tid + 256];
            dst[tid + 512] = src[tid + 512];
            dst[tid + 768] = src[tid + 768];
        }
        // Neighbor lookup.
        if (tid < TILE_V) {
            const int dz = k / 9 - 1, dy = (k / 3) % 3 - 1, dx = k % 3 - 1;
            int z = sZ[tid] + dz, y = sY[tid] + dy, x = sX[tid] + dx;
            int idx = -1;
            if ((unsigned)z < GD && (unsigned)y < GH && (unsigned)x < GW)
                idx = g_grid[(z * GH + y) * GW + x];
            sIdx[tid] = idx;
        }
        __syncthreads();

        // Gather: 128 voxels x 32 packed words. Warp = one voxel row (coalesced LDG,
        // conflict-free swizzled STS).
        #pragma unroll
        for (int s = 0; s < 16; s++) {
            int slot = s * 256 + tid;
            int v = slot >> 5;
            int c = slot & 31;
            int idx = sIdx[v];
            uint32_t w = 0;
            if (idx >= 0) w = g_packF[idx * CIN + c];
            sBuf[swz128((uint32_t)(v * 128 + c * 4)) >> 2] = w;
        }
        // Every writer orders its generic-proxy STS against the async proxy,
        // THEN the barrier publishes to the MMA-issuing thread.
        asm volatile("fence.proxy.async.shared::cta;" ::: "memory");
        __syncthreads();

        if (tid == 0) {
            #pragma unroll
            for (int s = 0; s < 4; s++)   // pass1: (ahi+alo) * whi
                mma_f16_ss(tmem, aDesc + s * 2, b1Desc + s * 2, (k == 0 && s == 0) ? 0u : 1u);
            #pragma unroll
            for (int s = 0; s < 4; s++)   // pass2: ahi * wlo
                mma_f16_ss(tmem, aDesc + s * 2, b2Desc + s * 2, 1u);
            asm volatile(
                "tcgen05.commit.cta_group::1.mbarrier::arrive::one.shared::cluster.b64 [%0];"
                :: "r"(mbarAddr) : "memory");
        }
    }

    MBARRIER_WAIT_PARITY(mbarAddr, (NK - 1) & 1);  // commit 26 -> parity 0
    asm volatile("tcgen05.fence::after_thread_sync;" ::: "memory");

    // Epilogue: warpgroup 0 (threads 0..127) reads TMEM rows = voxels.
    if (tid < 128) {
        uint32_t r[64];
        asm volatile(
            "tcgen05.ld.sync.aligned.32x32b.x32.b32 "
            "{%0,%1,%2,%3,%4,%5,%6,%7,%8,%9,%10,%11,%12,%13,%14,%15,"
            "%16,%17,%18,%19,%20,%21,%22,%23,%24,%25,%26,%27,%28,%29,%30,%31}, [%32];"
            : "=r"(r[0]),"=r"(r[1]),"=r"(r[2]),"=r"(r[3]),"=r"(r[4]),"=r"(r[5]),"=r"(r[6]),"=r"(r[7]),
              "=r"(r[8]),"=r"(r[9]),"=r"(r[10]),"=r"(r[11]),"=r"(r[12]),"=r"(r[13]),"=r"(r[14]),"=r"(r[15]),
              "=r"(r[16]),"=r"(r[17]),"=r"(r[18]),"=r"(r[19]),"=r"(r[20]),"=r"(r[21]),"=r"(r[22]),"=r"(r[23]),
              "=r"(r[24]),"=r"(r[25]),"=r"(r[26]),"=r"(r[27]),"=r"(r[28]),"=r"(r[29]),"=r"(r[30]),"=r"(r[31])
            : "r"(tmem));
        asm volatile(
            "tcgen05.ld.sync.aligned.32x32b.x32.b32 "
            "{%0,%1,%2,%3,%4,%5,%6,%7,%8,%9,%10,%11,%12,%13,%14,%15,"
            "%16,%17,%18,%19,%20,%21,%22,%23,%24,%25,%26,%27,%28,%29,%30,%31}, [%32];"
            : "=r"(r[32]),"=r"(r[33]),"=r"(r[34]),"=r"(r[35]),"=r"(r[36]),"=r"(r[37]),"=r"(r[38]),"=r"(r[39]),
              "=r"(r[40]),"=r"(r[41]),"=r"(r[42]),"=r"(r[43]),"=r"(r[44]),"=r"(r[45]),"=r"(r[46]),"=r"(r[47]),
              "=r"(r[48]),"=r"(r[49]),"=r"(r[50]),"=r"(r[51]),"=r"(r[52]),"=r"(r[53]),"=r"(r[54]),"=r"(r[55]),
              "=r"(r[56]),"=r"(r[57]),"=r"(r[58]),"=r"(r[59]),"=r"(r[60]),"=r"(r[61]),"=r"(r[62]),"=r"(r[63])
            : "r"(tmem + 32));
        asm volatile("tcgen05.wait::ld.sync.aligned;" ::: "memory");

        int v = v0 + tid;
        if (v < n) {
            float4* op = reinterpret_cast<float4*>(out + (size_t)v * COUT);
            #pragma unroll
            for (int j = 0; j < 16; j++) {
                float4 o;
                o.x = __uint_as_float(r[4 * j + 0]) + sBias[4 * j + 0];
                o.y = __uint_as_float(r[4 * j + 1]) + sBias[4 * j + 1];
                o.z = __uint_as_float(r[4 * j + 2]) + sBias[4 * j + 2];
                o.w = __uint_as_float(r[4 * j + 3]) + sBias[4 * j + 3];
                op[j] = o;
            }
        }
    }

    __syncthreads();
    if (tid == 0) {
        asm volatile("mbarrier.inval.shared.b64 [%0];" :: "r"(mbarAddr) : "memory");
    }
    if (tid < 32) {
        asm volatile("tcgen05.dealloc.cta_group::1.sync.aligned.b32 %0, %1;" :: "r"(tmem), "r"(64u));
    }
#endif  // HAS_TCGEN05
}

extern "C" void kernel_launch(void* const* d_in, const int* in_sizes, int n_in,
                              void* d_out, int out_size) {
    const float* feat   = (const float*)d_in[0];
    const int*   coors  = (const int*)d_in[1];
    const float* weight = (const float*)d_in[2];
    const float* bias   = (const float*)d_in[3];
    float* out = (float*)d_out;
    const int n = in_sizes[0] / CIN;

    init_grid_kernel<<<(GD * GH * GW / 4 + 255) / 256, 256>>>();
    scatter_kernel<<<(n + 255) / 256, 256>>>(coors, n);
    pack_features_kernel<<<(n * CIN + 255) / 256, 256>>>(feat, n * CIN);
    pack_weights_kernel<<<(NK * COUT * CIN + 255) / 256, 256>>>(weight);
    conv_tc_kernel<<<(n + TILE_V - 1) / TILE_V, 256>>>(coors, bias, out, n);
}